// round 6
// baseline (speedup 1.0000x reference)
#include <cuda_runtime.h>
#include <cuda_bf16.h>
#include <cstdint>

#define IMG_W 512
#define IMG_H 512
#define SUBROWS 32
#define NTHREADS 128

// Packed f32x2 helpers (Blackwell sm_103a): 2 fp32 lanes in one 64-bit reg.
#define F2U(f)            __float_as_uint(f)
#define U2F(u)            __uint_as_float(u)
#define X2_ADD(d, a, b)   asm("add.rn.f32x2 %0, %1, %2;" : "=l"(d) : "l"(a), "l"(b))
#define X2_MUL(d, a, b)   asm("mul.rn.f32x2 %0, %1, %2;" : "=l"(d) : "l"(a), "l"(b))
#define X2_FMA(d, a, b, c) asm("fma.rn.f32x2 %0, %1, %2, %3;" : "=l"(d) : "l"(a), "l"(b), "l"(c))
#define X2_PACK(d, lo, hi) asm("mov.b64 %0, {%1, %2};" : "=l"(d) : "r"(lo), "r"(hi))
#define X2_UNPACK(lo, hi, s) asm("mov.b64 {%0, %1}, %2;" : "=r"(lo), "=r"(hi) : "l"(s))

// 3x3 local variance, stride 1, zero pad 1, divisor 9.
// Each lane owns 8 contiguous columns (4 f32x2 pairs, 2x LDG.128/row).
// Rolling packed state: vp2 (prev row), p2 (2-row sum), q2 (2-row sq-sum).
// Vertical 3-sum then horizontal 3-tap, all in packed f32x2; warp-boundary
// column handled by shuffles + scalar rolling state in lanes 0/31.
__global__ __launch_bounds__(NTHREADS, 8)
void ChannelwiseVariance_85091892068508_kernel(const float* __restrict__ x,
                                               float* __restrict__ out)
{
    const int tid  = threadIdx.x;
    const int lane = tid & 31;
    const int w    = tid >> 5;
    const int colhalf = w & 1;
    const int sub     = w >> 1;
    const int col  = colhalf * 256 + lane * 8;
    const int y0   = blockIdx.x * (2 * SUBROWS) + sub * SUBROWS;
    const size_t plane = (size_t)blockIdx.y * (size_t)(IMG_H * IMG_W);

    const bool has_left  = (col != 0);
    const bool has_right = (col + 8 != IMG_W);
    const float inv9 = 1.0f / 9.0f;
    uint64_t inv9x2; X2_PACK(inv9x2, F2U(inv9), F2U(inv9));

    uint64_t vp2[4], p2[4], q2[4];
    #pragma unroll
    for (int k = 0; k < 4; ++k) { vp2[k] = 0ull; p2[k] = 0ull; q2[k] = 0ull; }
    // boundary-column scalar rolling state (lanes 0 / 31)
    float lxp = 0.f, lp = 0.f, lq = 0.f;
    float rxp = 0.f, rp = 0.f, rq = 0.f;

    #pragma unroll 2
    for (int it = 0; it < SUBROWS + 2; ++it) {
        const int r = y0 - 1 + it;
        const bool rvalid = (r >= 0) && (r < IMG_H);
        const size_t rowoff = plane + (size_t)r * IMG_W;

        float4 va = make_float4(0.f, 0.f, 0.f, 0.f);
        float4 vb = make_float4(0.f, 0.f, 0.f, 0.f);
        float lxn = 0.f, rxn = 0.f;
        if (rvalid) {
            va = *reinterpret_cast<const float4*>(x + rowoff + col);
            vb = *reinterpret_cast<const float4*>(x + rowoff + col + 4);
        }
        if (lane == 0 && rvalid && has_left)   lxn = x[rowoff + col - 1];
        if (lane == 31 && rvalid && has_right) rxn = x[rowoff + col + 8];

        uint64_t vc2[4];
        X2_PACK(vc2[0], F2U(va.x), F2U(va.y));
        X2_PACK(vc2[1], F2U(va.z), F2U(va.w));
        X2_PACK(vc2[2], F2U(vb.x), F2U(vb.y));
        X2_PACK(vc2[3], F2U(vb.z), F2U(vb.w));

        // Vertical 3-sums (S1,S2 for output row r-1), roll state forward.
        uint64_t S1[4], S2[4];
        #pragma unroll
        for (int k = 0; k < 4; ++k) {
            uint64_t sq;
            X2_MUL(sq, vc2[k], vc2[k]);
            X2_ADD(S1[k], p2[k], vc2[k]);
            X2_ADD(S2[k], q2[k], sq);
            X2_ADD(p2[k], vp2[k], vc2[k]);
            X2_FMA(q2[k], vp2[k], vp2[k], sq);
            vp2[k] = vc2[k];
        }
        // Boundary scalar chain.
        const float lsq = lxn * lxn, rsq = rxn * rxn;
        const float lS1 = lp + lxn, lS2 = lq + lsq;
        const float rS1 = rp + rxn, rS2 = rq + rsq;
        lp = lxp + lxn; lq = fmaf(lxp, lxp, lsq); lxp = lxn;
        rp = rxp + rxn; rq = fmaf(rxp, rxp, rsq); rxp = rxn;

        if (it >= 2) {
            // Unpack S1/S2 pair components (needed for shifted repack + shuffle).
            uint32_t a_lo[4], a_hi[4], b_lo[4], b_hi[4];
            #pragma unroll
            for (int k = 0; k < 4; ++k) {
                X2_UNPACK(a_lo[k], a_hi[k], S1[k]);
                X2_UNPACK(b_lo[k], b_hi[k], S2[k]);
            }
            // Warp halo (vertical sums of col-1 / col+8).
            uint32_t svl = __shfl_up_sync(0xffffffffu, a_hi[3], 1);
            uint32_t sql = __shfl_up_sync(0xffffffffu, b_hi[3], 1);
            uint32_t svr = __shfl_down_sync(0xffffffffu, a_lo[0], 1);
            uint32_t sqr = __shfl_down_sync(0xffffffffu, b_lo[0], 1);
            if (lane == 0)  { svl = F2U(lS1); sql = F2U(lS2); }
            if (lane == 31) { svr = F2U(rS1); sqr = F2U(rS2); }

            // s[0..9] = {halo_l, S1[0..7], halo_r}; t[j] = s[j]+s[j+1]+s[j+2].
            // W0[k]=(s[2k],s[2k+1]) k=0..4, W1[k]=S1pair[k], W2[k]=W0[k+1].
            uint64_t W0a[5], W0b[5];
            X2_PACK(W0a[0], svl,     a_lo[0]);
            X2_PACK(W0a[1], a_hi[0], a_lo[1]);
            X2_PACK(W0a[2], a_hi[1], a_lo[2]);
            X2_PACK(W0a[3], a_hi[2], a_lo[3]);
            X2_PACK(W0a[4], a_hi[3], svr);
            X2_PACK(W0b[0], sql,     b_lo[0]);
            X2_PACK(W0b[1], b_hi[0], b_lo[1]);
            X2_PACK(W0b[2], b_hi[1], b_lo[2]);
            X2_PACK(W0b[3], b_hi[2], b_lo[3]);
            X2_PACK(W0b[4], b_hi[3], sqr);

            uint64_t o2[4];
            #pragma unroll
            for (int k = 0; k < 4; ++k) {
                uint64_t t1, t2, m, mm, s2i;
                X2_ADD(t1, W0a[k], S1[k]);
                X2_ADD(t1, t1, W0a[k + 1]);
                X2_ADD(t2, W0b[k], S2[k]);
                X2_ADD(t2, t2, W0b[k + 1]);
                X2_MUL(m, t1, inv9x2);
                X2_MUL(mm, m, m);
                X2_MUL(s2i, t2, inv9x2);
                // o = s2i - mm  (sub via add of negated mm: flip sign bits)
                uint64_t nmm = mm ^ 0x8000000080000000ull;
                X2_ADD(o2[k], s2i, nmm);
            }

            uint32_t o_lo[4], o_hi[4];
            #pragma unroll
            for (int k = 0; k < 4; ++k) X2_UNPACK(o_lo[k], o_hi[k], o2[k]);

            const int y = r - 1;
            float* op = out + plane + (size_t)y * IMG_W + col;
            __stcs(reinterpret_cast<float4*>(op),
                   make_float4(U2F(o_lo[0]), U2F(o_hi[0]), U2F(o_lo[1]), U2F(o_hi[1])));
            __stcs(reinterpret_cast<float4*>(op + 4),
                   make_float4(U2F(o_lo[2]), U2F(o_hi[2]), U2F(o_lo[3]), U2F(o_hi[3])));
        }
    }
}

extern "C" void kernel_launch(void* const* d_in, const int* in_sizes, int n_in,
                              void* d_out, int out_size)
{
    const float* x = (const float*)d_in[0];
    float* out = (float*)d_out;

    const int planes = in_sizes[0] / (IMG_H * IMG_W);   // 8*32 = 256
    dim3 grid(IMG_H / (2 * SUBROWS), planes);           // (8, 256) = 2048 blocks
    dim3 block(NTHREADS);
    ChannelwiseVariance_85091892068508_kernel<<<grid, block>>>(x, out);
}